// round 2
// baseline (speedup 1.0000x reference)
#include <cuda_runtime.h>
#include <cstdint>

// FioraModel double_softmax, 2 graphs per warp.
// Per graph g (256 contiguous flat edge values v[0..255], scalar gv):
//   m     = max(max_j v[j], gv)
//   e_j   = exp(v[j]-m),  e_g = exp(gv-m)
//   denom = sum_j e_j + 2*e_g
//   out[258*g + j]       = 2*e_j / denom   (j = 0..255)
//   out[258*g + 256/257] = 2*e_g / denom
//
// Two graphs per warp: 4 front-batched LDG.128 (MLP_p1=4), and the two
// independent shuffle-reduction chains overlap (ILP=2 across SHFL/MUFU
// latency). Streaming hints (__ldcs/__stcs) since the 206MB stream is
// 1.6x L2.

static constexpr int OUT_PER_GRAPH = 258;
static constexpr unsigned FULL = 0xffffffffu;

__device__ __forceinline__ float max8(const float4& a, const float4& b) {
    return fmaxf(fmaxf(fmaxf(a.x, a.y), fmaxf(a.z, a.w)),
                 fmaxf(fmaxf(b.x, b.y), fmaxf(b.z, b.w)));
}

__global__ __launch_bounds__(256, 8)
void fiora_double_softmax2_kernel(const float4* __restrict__ ev4,
                                  const float*  __restrict__ gv,
                                  float*        __restrict__ out,
                                  int G)
{
    const int warp = (blockIdx.x * blockDim.x + threadIdx.x) >> 5;
    const int lane = threadIdx.x & 31;
    const int gA = warp * 2;
    const int gB = gA + 1;
    if (gA >= G) return;
    const bool hasB = (gB < G);

    // ---- front-batched loads: 4 independent LDG.128 ----
    const float4* baseA = ev4 + (size_t)gA * 64;
    const float4* baseB = ev4 + (size_t)gB * 64;
    float4 a0 = __ldcs(baseA + lane);
    float4 a1 = __ldcs(baseA + lane + 32);
    float4 b0, b1;
    float  gvB = 0.0f;
    if (hasB) {
        b0  = __ldcs(baseB + lane);
        b1  = __ldcs(baseB + lane + 32);
        gvB = __ldg(gv + gB);
    } else {
        b0 = b1 = make_float4(0.f, 0.f, 0.f, 0.f);
    }
    float gvA = __ldg(gv + gA);

    // ---- interleaved max reductions ----
    float mA = fmaxf(max8(a0, a1), gvA);
    float mB = fmaxf(max8(b0, b1), gvB);
    #pragma unroll
    for (int o = 16; o > 0; o >>= 1) {
        mA = fmaxf(mA, __shfl_xor_sync(FULL, mA, o));
        mB = fmaxf(mB, __shfl_xor_sync(FULL, mB, o));
    }

    // ---- exp (16 independent MUFUs) ----
    float ea0 = __expf(a0.x - mA), ea1 = __expf(a0.y - mA);
    float ea2 = __expf(a0.z - mA), ea3 = __expf(a0.w - mA);
    float ea4 = __expf(a1.x - mA), ea5 = __expf(a1.y - mA);
    float ea6 = __expf(a1.z - mA), ea7 = __expf(a1.w - mA);
    float eb0 = __expf(b0.x - mB), eb1 = __expf(b0.y - mB);
    float eb2 = __expf(b0.z - mB), eb3 = __expf(b0.w - mB);
    float eb4 = __expf(b1.x - mB), eb5 = __expf(b1.y - mB);
    float eb6 = __expf(b1.z - mB), eb7 = __expf(b1.w - mB);

    // ---- interleaved sum reductions ----
    float sA = ((ea0 + ea1) + (ea2 + ea3)) + ((ea4 + ea5) + (ea6 + ea7));
    float sB = ((eb0 + eb1) + (eb2 + eb3)) + ((eb4 + eb5) + (eb6 + eb7));
    #pragma unroll
    for (int o = 16; o > 0; o >>= 1) {
        sA += __shfl_xor_sync(FULL, sA, o);
        sB += __shfl_xor_sync(FULL, sB, o);
    }

    float egA   = __expf(gvA - mA);
    float egB   = __expf(gvB - mB);
    float invA  = __fdividef(2.0f, sA + 2.0f * egA);
    float invB  = __fdividef(2.0f, sB + 2.0f * egB);

    // ---- streaming float2 stores ----
    float2* obA = reinterpret_cast<float2*>(out + (size_t)gA * OUT_PER_GRAPH);
    __stcs(obA + 2 * lane + 0,        make_float2(ea0 * invA, ea1 * invA));
    __stcs(obA + 2 * lane + 1,        make_float2(ea2 * invA, ea3 * invA));
    __stcs(obA + 2 * (lane + 32) + 0, make_float2(ea4 * invA, ea5 * invA));
    __stcs(obA + 2 * (lane + 32) + 1, make_float2(ea6 * invA, ea7 * invA));
    if (lane == 0) {
        float go = egA * invA;
        __stcs(obA + 128, make_float2(go, go));   // out[256], out[257]
    }

    if (hasB) {
        float2* obB = reinterpret_cast<float2*>(out + (size_t)gB * OUT_PER_GRAPH);
        __stcs(obB + 2 * lane + 0,        make_float2(eb0 * invB, eb1 * invB));
        __stcs(obB + 2 * lane + 1,        make_float2(eb2 * invB, eb3 * invB));
        __stcs(obB + 2 * (lane + 32) + 0, make_float2(eb4 * invB, eb5 * invB));
        __stcs(obB + 2 * (lane + 32) + 1, make_float2(eb6 * invB, eb7 * invB));
        if (lane == 1) {                       // different lane: overlap with lane 0's store
            float go = egB * invB;
            __stcs(obB + 128, make_float2(go, go));
        }
    }
}

extern "C" void kernel_launch(void* const* d_in, const int* in_sizes, int n_in,
                              void* d_out, int out_size)
{
    const float* edge_values  = (const float*)d_in[0];   // [G*EPG, D] fp32
    const float* graph_values = (const float*)d_in[1];   // [G, 1]     fp32
    const int G = in_sizes[1];

    // 8 warps/block, 2 graphs/warp -> 16 graphs per block of 256 threads
    const int graphs_per_block = 16;
    const int blocks = (G + graphs_per_block - 1) / graphs_per_block;

    fiora_double_softmax2_kernel<<<blocks, 256>>>(
        (const float4*)edge_values, graph_values, (float*)d_out, G);
}